// round 2
// baseline (speedup 1.0000x reference)
#include <cuda_runtime.h>
#include <cstdint>

// Problem constants
#define NN   4096
#define INF  256
#define Hh   4
#define Dd   64
#define HD   256         // Hh*Dd
#define TI   64          // i-rows per CTA in aggregation
#define JC   32          // j-chunk
#define JSPLIT 2
#define JPER (NN/JSPLIT) // 2048
#define NCHUNK (JPER/JC) // 64

using u64 = unsigned long long;

// ---------------- device scratch (no runtime allocation allowed) -------------
__device__ float g_h[NN*HD];             // 4 MB : h = x@W
__device__ float g_si[NN*Hh];
__device__ float g_sj[NN*Hh];
__device__ float g_eip[NN*Hh];           // exp(si)
__device__ float g_ein[NN*Hh];           // exp(0.2*si)
__device__ float g_ejp[NN*Hh];           // exp(sj)
__device__ float g_ejn[NN*Hh];           // exp(0.2*sj)
__device__ float g_part[JSPLIT*NN*HD];   // 8 MB partial accumulators
__device__ float g_Z[JSPLIT*NN*Hh];      // partial normalizers

// ---------------- f32x2 packed helpers ---------------------------------------
__device__ __forceinline__ u64 pack2(float x, float y) {
    u64 r; asm("mov.b64 %0, {%1,%2};" : "=l"(r) : "f"(x), "f"(y)); return r;
}
__device__ __forceinline__ float2 unpack2(u64 v) {
    float2 r; asm("mov.b64 {%0,%1}, %2;" : "=f"(r.x), "=f"(r.y) : "l"(v)); return r;
}
__device__ __forceinline__ u64 fma2(u64 a, u64 b, u64 c) {
    u64 d; asm("fma.rn.f32x2 %0, %1, %2, %3;" : "=l"(d) : "l"(a), "l"(b), "l"(c));
    return d;
}

// ---------------- kernel 1: h = x @ W  (64x64 tiles, f32x2) ------------------
__global__ void __launch_bounds__(256) gemm_xw(const float* __restrict__ x,
                                               const float* __restrict__ W) {
    __shared__ float As[16*64];   // [k][m]
    __shared__ float Bs[16*64];   // [k][n]
    const int t = threadIdx.x;
    const int row0 = blockIdx.y * 64;
    const int col0 = blockIdx.x * 64;
    const int tx = t & 15;        // n-tile
    const int ty = t >> 4;        // m-tile (0..15)

    u64 acc[2][4];
    #pragma unroll
    for (int m = 0; m < 2; m++)
        #pragma unroll
        for (int n = 0; n < 4; n++) acc[m][n] = 0ull;

    for (int kb = 0; kb < INF; kb += 16) {
        {
            const int aRow = t >> 2;
            const int aK4  = (t & 3) * 4;
            float4 av = *(const float4*)(x + (size_t)(row0 + aRow) * INF + kb + aK4);
            As[(aK4 + 0) * 64 + aRow] = av.x;
            As[(aK4 + 1) * 64 + aRow] = av.y;
            As[(aK4 + 2) * 64 + aRow] = av.z;
            As[(aK4 + 3) * 64 + aRow] = av.w;
        }
        {
            const int bK  = t >> 4;
            const int bN4 = (t & 15) * 4;
            *(float4*)&Bs[bK * 64 + bN4] =
                *(const float4*)(W + (size_t)(kb + bK) * HD + col0 + bN4);
        }
        __syncthreads();
        #pragma unroll
        for (int k = 0; k < 16; k++) {
            float4 a4 = *(const float4*)&As[k * 64 + ty * 4];
            float4 b4 = *(const float4*)&Bs[k * 64 + tx * 4];
            u64 a01 = pack2(a4.x, a4.y);
            u64 a23 = pack2(a4.z, a4.w);
            u64 bb0 = pack2(b4.x, b4.x), bb1 = pack2(b4.y, b4.y);
            u64 bb2 = pack2(b4.z, b4.z), bb3 = pack2(b4.w, b4.w);
            acc[0][0] = fma2(a01, bb0, acc[0][0]); acc[1][0] = fma2(a23, bb0, acc[1][0]);
            acc[0][1] = fma2(a01, bb1, acc[0][1]); acc[1][1] = fma2(a23, bb1, acc[1][1]);
            acc[0][2] = fma2(a01, bb2, acc[0][2]); acc[1][2] = fma2(a23, bb2, acc[1][2]);
            acc[0][3] = fma2(a01, bb3, acc[0][3]); acc[1][3] = fma2(a23, bb3, acc[1][3]);
        }
        __syncthreads();
    }
    #pragma unroll
    for (int mp = 0; mp < 2; mp++) {
        #pragma unroll
        for (int n = 0; n < 4; n++) {
            float2 v = unpack2(acc[mp][n]);
            int r0 = row0 + ty * 4 + mp * 2;
            g_h[(size_t)(r0 + 0) * HD + col0 + tx * 4 + n] = v.x;
            g_h[(size_t)(r0 + 1) * HD + col0 + tx * 4 + n] = v.y;
        }
    }
}

// ---------------- kernel 2: per (node, head) scores + exp tables -------------
__global__ void __launch_bounds__(256) scores_k(const float* __restrict__ a1,
                                                const float* __restrict__ a2) {
    __shared__ float s1[Dd], s2[Dd];
    if (threadIdx.x < Dd)            s1[threadIdx.x]      = a1[threadIdx.x];
    else if (threadIdx.x < 2 * Dd)   s2[threadIdx.x - Dd] = a2[threadIdx.x - Dd];
    __syncthreads();

    const int g  = blockIdx.x * 256 + threadIdx.x;   // 0..N*H-1
    const int n  = g >> 2;
    const int hh = g & 3;
    const float* hrow = g_h + (size_t)n * HD + hh * Dd;
    float si = 0.f, sj = 0.f;
    #pragma unroll
    for (int q = 0; q < 16; q++) {
        float4 hv = ((const float4*)hrow)[q];
        si = fmaf(hv.x, s1[4*q+0], si); sj = fmaf(hv.x, s2[4*q+0], sj);
        si = fmaf(hv.y, s1[4*q+1], si); sj = fmaf(hv.y, s2[4*q+1], sj);
        si = fmaf(hv.z, s1[4*q+2], si); sj = fmaf(hv.z, s2[4*q+2], sj);
        si = fmaf(hv.w, s1[4*q+3], si); sj = fmaf(hv.w, s2[4*q+3], sj);
    }
    g_si[g]  = si;                 g_sj[g]  = sj;
    g_eip[g] = __expf(si);         g_ejp[g] = __expf(sj);
    g_ein[g] = __expf(0.2f * si);  g_ejn[g] = __expf(0.2f * sj);
}

// ---------------- kernel 3: fused masked-softmax aggregation -----------------
// 512 threads. grid (64 i-tiles, 2 j-splits).
// smem: hS [JC][H][2][9 f4] padded (9216 f) | wS [JC] x 260 f (8320 f)
//       | sjS/ejpS/ejnS [JC][H] (3*128 f)
#define HS_F4_PER_J   72    // H * 18 float4
#define WS_STRIDE     260   // TI*Hh + 4 pad floats per j
#define SMEM_FLOATS  (JC*288 + JC*WS_STRIDE + 3*JC*Hh)
#define SMEM_BYTES   (SMEM_FLOATS * 4)

__global__ void __launch_bounds__(512, 1) gat_agg(const int* __restrict__ adj) {
    extern __shared__ float sm[];
    float* hS   = sm;                         // JC*288
    float* wS   = sm + JC * 288;              // JC*260
    float* sjS  = wS + JC * WS_STRIDE;        // JC*H
    float* ejpS = sjS + JC * Hh;
    float* ejnS = ejpS + JC * Hh;

    const int t     = threadIdx.x;
    const int i0    = blockIdx.x * TI;
    const int split = blockIdx.y;
    const int jbase0 = split * JPER;

    // Phase-B ids: 1 i x 1 head x 32 d per thread
    const int head  = t & 3;
    const int dhalf = (t >> 2) & 1;
    const int iB    = t >> 3;                 // 0..63

    // Phase-A ids: one i-row, 4 j's strided by 8
    const int iA = t >> 3;                    // 0..63
    const int jg = t & 7;                     // 0..7

    // hoisted per-i score/exp values (float4 over heads)
    const float4 rsi  = ((const float4*)g_si )[i0 + iA];
    const float4 reip = ((const float4*)g_eip)[i0 + iA];
    const float4 rein = ((const float4*)g_ein)[i0 + iA];

    u64 acc[16];
    #pragma unroll
    for (int q = 0; q < 16; q++) acc[q] = 0ull;
    float Z = 0.f;

    for (int c = 0; c < NCHUNK; c++) {
        const int jb = jbase0 + c * JC;
        __syncthreads();   // previous Phase B done before smem overwrite

        // stage sj / exp tables ([JC][H] contiguous, 128 each)
        if (t < 128)       sjS [t]       = g_sj [jb * Hh + t];
        else if (t < 256)  ejpS[t - 128] = g_ejp[jb * Hh + t - 128];
        else if (t < 384)  ejnS[t - 256] = g_ejn[jb * Hh + t - 256];

        // stage h tile: [j][h][dhalf] padded-half layout
        {
            const float4* src = (const float4*)(g_h + (size_t)jb * HD);
            #pragma unroll
            for (int r = 0; r < 4; r++) {
                int v = r * 512 + t;            // float4 index within chunk
                float4 val = src[v];
                int j = v >> 6, rem = v & 63;
                int hh2 = rem >> 4, q = rem & 15;
                int dh = q >> 3, qq = q & 7;
                ((float4*)hS)[j * HS_F4_PER_J + hh2 * 18 + dh * 9 + qq] = val;
            }
        }
        __syncthreads();

        // Phase A: build weight tile wS[j][i*4+h], j = jg + 8*jj
        {
            const int* arow = adj + (size_t)(i0 + iA) * NN + jb + jg;
            #pragma unroll
            for (int jj = 0; jj < 4; jj++) {
                const int j = jg + 8 * jj;
                const bool edge = arow[8 * jj] > 0;
                float4 sj4  = ((const float4*)sjS )[j];
                float4 ejp4 = ((const float4*)ejpS)[j];
                float4 ejn4 = ((const float4*)ejnS)[j];
                float4 wv;
                float wpx = reip.x * ejp4.x, wnx = rein.x * ejn4.x;
                float wpy = reip.y * ejp4.y, wny = rein.y * ejn4.y;
                float wpz = reip.z * ejp4.z, wnz = rein.z * ejn4.z;
                float wpw = reip.w * ejp4.w, wnw = rein.w * ejn4.w;
                wv.x = (rsi.x + sj4.x >= 0.f) ? wpx : wnx;
                wv.y = (rsi.y + sj4.y >= 0.f) ? wpy : wny;
                wv.z = (rsi.z + sj4.z >= 0.f) ? wpz : wnz;
                wv.w = (rsi.w + sj4.w >= 0.f) ? wpw : wnw;
                if (!edge) { wv.x = 0.f; wv.y = 0.f; wv.z = 0.f; wv.w = 0.f; }
                *(float4*)&wS[j * WS_STRIDE + iA * 4] = wv;
            }
        }
        __syncthreads();

        // Phase B: FMA-bound accumulation (f32x2 packed), 1 i per thread
        #pragma unroll 2
        for (int j = 0; j < JC; j++) {
            float w = wS[j * WS_STRIDE + iB * 4 + head];
            Z += w;
            u64 W2 = pack2(w, w);
            const float4* hp = ((const float4*)hS) + j * HS_F4_PER_J + head * 18 + dhalf * 9;
            #pragma unroll
            for (int q = 0; q < 8; q++) {
                float4 hv = hp[q];
                acc[2*q]   = fma2(pack2(hv.x, hv.y), W2, acc[2*q]);
                acc[2*q+1] = fma2(pack2(hv.z, hv.w), W2, acc[2*q+1]);
            }
        }
    }

    // writeback partials
    {
        float* base = g_part + (size_t)split * NN * HD
                    + (size_t)(i0 + iB) * HD + head * Dd + dhalf * 32;
        #pragma unroll
        for (int q = 0; q < 16; q++) ((float2*)base)[q] = unpack2(acc[q]);
        if (dhalf == 0)
            g_Z[(size_t)split * NN * Hh + (i0 + iB) * Hh + head] = Z;
    }
}

// ---------------- kernel 4: combine splits + normalize -----------------------
__global__ void __launch_bounds__(256) epilogue_k(float* __restrict__ out) {
    int e = blockIdx.x * 256 + threadIdx.x;      // 0..N*HD-1
    float p = g_part[e] + g_part[(size_t)NN * HD + e];
    int i = e >> 8;
    int head = (e & 255) >> 6;
    float z = g_Z[i * Hh + head] + g_Z[(size_t)NN * Hh + i * Hh + head];
    out[e] = p / z;
}

// ---------------- launch ------------------------------------------------------
extern "C" void kernel_launch(void* const* d_in, const int* in_sizes, int n_in,
                              void* d_out, int out_size) {
    const float* x   = (const float*)d_in[0];
    const int*   adj = (const int*)  d_in[1];
    const float* W   = (const float*)d_in[2];
    const float* a1  = (const float*)d_in[3];
    const float* a2  = (const float*)d_in[4];
    float* out = (float*)d_out;

    cudaFuncSetAttribute(gat_agg, cudaFuncAttributeMaxDynamicSharedMemorySize, SMEM_BYTES);

    gemm_xw  <<<dim3(HD/64, NN/64), 256>>>(x, W);
    scores_k <<<(NN*Hh)/256, 256>>>(a1, a2);
    gat_agg  <<<dim3(NN/TI, JSPLIT), 512, SMEM_BYTES>>>(adj);
    epilogue_k<<<(NN*HD)/256, 256>>>(out);
}

// round 4
// speedup vs baseline: 3.1498x; 3.1498x over previous
#include <cuda_runtime.h>
#include <cuda_fp16.h>
#include <cstdint>

// Problem constants
#define NN   4096
#define INF  256
#define Hh   4
#define Dd   64
#define HD   256         // Hh*Dd
#define TI   64          // i-rows per CTA in aggregation
#define JC   64          // j-chunk for MMA kernel
#define JSPLIT 2
#define JPER (NN/JSPLIT) // 2048
#define NCHUNK (JPER/JC) // 32

using u64 = unsigned long long;
using u32 = unsigned int;

// ---------------- device scratch ---------------------------------------------
__device__ float  g_h [NN*HD];            // fp32 h = x@W (for scores)
__device__ __half g_hh[NN*HD];            // fp16 copy (MMA B operand)
__device__ float g_si[NN*Hh];
__device__ float g_sj[NN*Hh];
__device__ float g_eip[NN*Hh];
__device__ float g_ein[NN*Hh];
__device__ float g_ejp[NN*Hh];
__device__ float g_ejn[NN*Hh];
__device__ float g_part[JSPLIT*NN*HD];    // partial accumulators
__device__ float g_Z[JSPLIT*NN*Hh];       // partial normalizers

// ---------------- f32x2 packed helpers ---------------------------------------
__device__ __forceinline__ u64 pack2(float x, float y) {
    u64 r; asm("mov.b64 %0, {%1,%2};" : "=l"(r) : "f"(x), "f"(y)); return r;
}
__device__ __forceinline__ float2 unpack2(u64 v) {
    float2 r; asm("mov.b64 {%0,%1}, %2;" : "=f"(r.x), "=f"(r.y) : "l"(v)); return r;
}
__device__ __forceinline__ u64 fma2(u64 a, u64 b, u64 c) {
    u64 d; asm("fma.rn.f32x2 %0, %1, %2, %3;" : "=l"(d) : "l"(a), "l"(b), "l"(c));
    return d;
}
// bit-cast __half2 -> u32 (toolkit-safe)
__device__ __forceinline__ u32 h2_u32(__half2 v) {
    __half2_raw r = *(__half2_raw*)&v;
    return (u32)r.x | ((u32)r.y << 16);
}

// ---------------- mma / ldmatrix helpers --------------------------------------
__device__ __forceinline__ void ldsm_x4(u32& r0, u32& r1, u32& r2, u32& r3, u32 addr) {
    asm volatile("ldmatrix.sync.aligned.m8n8.x4.shared.b16 {%0,%1,%2,%3}, [%4];"
                 : "=r"(r0), "=r"(r1), "=r"(r2), "=r"(r3) : "r"(addr));
}
__device__ __forceinline__ void ldsm_x4_t(u32& r0, u32& r1, u32& r2, u32& r3, u32 addr) {
    asm volatile("ldmatrix.sync.aligned.m8n8.x4.trans.shared.b16 {%0,%1,%2,%3}, [%4];"
                 : "=r"(r0), "=r"(r1), "=r"(r2), "=r"(r3) : "r"(addr));
}
__device__ __forceinline__ void mma16816(float* c, u32 a0, u32 a1, u32 a2, u32 a3,
                                         u32 b0, u32 b1) {
    asm volatile("mma.sync.aligned.m16n8k16.row.col.f32.f16.f16.f32 "
                 "{%0,%1,%2,%3},{%4,%5,%6,%7},{%8,%9},{%0,%1,%2,%3};"
                 : "+f"(c[0]), "+f"(c[1]), "+f"(c[2]), "+f"(c[3])
                 : "r"(a0), "r"(a1), "r"(a2), "r"(a3), "r"(b0), "r"(b1));
}

// ---------------- kernel 1: h = x @ W  (also writes fp16 copy) ----------------
__global__ void __launch_bounds__(256) gemm_xw(const float* __restrict__ x,
                                               const float* __restrict__ W) {
    __shared__ float As[16*64];   // [k][m]
    __shared__ float Bs[16*64];   // [k][n]
    const int t = threadIdx.x;
    const int row0 = blockIdx.y * 64;
    const int col0 = blockIdx.x * 64;
    const int tx = t & 15;
    const int ty = t >> 4;

    u64 acc[2][4];
    #pragma unroll
    for (int m = 0; m < 2; m++)
        #pragma unroll
        for (int n = 0; n < 4; n++) acc[m][n] = 0ull;

    for (int kb = 0; kb < INF; kb += 16) {
        {
            const int aRow = t >> 2;
            const int aK4  = (t & 3) * 4;
            float4 av = *(const float4*)(x + (size_t)(row0 + aRow) * INF + kb + aK4);
            As[(aK4 + 0) * 64 + aRow] = av.x;
            As[(aK4 + 1) * 64 + aRow] = av.y;
            As[(aK4 + 2) * 64 + aRow] = av.z;
            As[(aK4 + 3) * 64 + aRow] = av.w;
        }
        {
            const int bK  = t >> 4;
            const int bN4 = (t & 15) * 4;
            *(float4*)&Bs[bK * 64 + bN4] =
                *(const float4*)(W + (size_t)(kb + bK) * HD + col0 + bN4);
        }
        __syncthreads();
        #pragma unroll
        for (int k = 0; k < 16; k++) {
            float4 a4 = *(const float4*)&As[k * 64 + ty * 4];
            float4 b4 = *(const float4*)&Bs[k * 64 + tx * 4];
            u64 a01 = pack2(a4.x, a4.y);
            u64 a23 = pack2(a4.z, a4.w);
            u64 bb0 = pack2(b4.x, b4.x), bb1 = pack2(b4.y, b4.y);
            u64 bb2 = pack2(b4.z, b4.z), bb3 = pack2(b4.w, b4.w);
            acc[0][0] = fma2(a01, bb0, acc[0][0]); acc[1][0] = fma2(a23, bb0, acc[1][0]);
            acc[0][1] = fma2(a01, bb1, acc[0][1]); acc[1][1] = fma2(a23, bb1, acc[1][1]);
            acc[0][2] = fma2(a01, bb2, acc[0][2]); acc[1][2] = fma2(a23, bb2, acc[1][2]);
            acc[0][3] = fma2(a01, bb3, acc[0][3]); acc[1][3] = fma2(a23, bb3, acc[1][3]);
        }
        __syncthreads();
    }
    #pragma unroll
    for (int mp = 0; mp < 2; mp++) {
        float2 v[4];
        #pragma unroll
        for (int n = 0; n < 4; n++) v[n] = unpack2(acc[mp][n]);
        int r0 = row0 + ty * 4 + mp * 2;
        int c0 = col0 + tx * 4;
        #pragma unroll
        for (int n = 0; n < 4; n++) {
            g_h[(size_t)(r0 + 0) * HD + c0 + n] = v[n].x;
            g_h[(size_t)(r0 + 1) * HD + c0 + n] = v[n].y;
        }
        __half2 hx0 = __floats2half2_rn(v[0].x, v[1].x);
        __half2 hx1 = __floats2half2_rn(v[2].x, v[3].x);
        __half2 hy0 = __floats2half2_rn(v[0].y, v[1].y);
        __half2 hy1 = __floats2half2_rn(v[2].y, v[3].y);
        *(__half2*)&g_hh[(size_t)(r0 + 0) * HD + c0]     = hx0;
        *(__half2*)&g_hh[(size_t)(r0 + 0) * HD + c0 + 2] = hx1;
        *(__half2*)&g_hh[(size_t)(r0 + 1) * HD + c0]     = hy0;
        *(__half2*)&g_hh[(size_t)(r0 + 1) * HD + c0 + 2] = hy1;
    }
}

// ---------------- kernel 2: scores + exp tables -------------------------------
__global__ void __launch_bounds__(256) scores_k(const float* __restrict__ a1,
                                                const float* __restrict__ a2) {
    __shared__ float s1[Dd], s2[Dd];
    if (threadIdx.x < Dd)            s1[threadIdx.x]      = a1[threadIdx.x];
    else if (threadIdx.x < 2 * Dd)   s2[threadIdx.x - Dd] = a2[threadIdx.x - Dd];
    __syncthreads();

    const int g  = blockIdx.x * 256 + threadIdx.x;
    const int n  = g >> 2;
    const int hh = g & 3;
    const float* hrow = g_h + (size_t)n * HD + hh * Dd;
    float si = 0.f, sj = 0.f;
    #pragma unroll
    for (int q = 0; q < 16; q++) {
        float4 hv = ((const float4*)hrow)[q];
        si = fmaf(hv.x, s1[4*q+0], si); sj = fmaf(hv.x, s2[4*q+0], sj);
        si = fmaf(hv.y, s1[4*q+1], si); sj = fmaf(hv.y, s2[4*q+1], sj);
        si = fmaf(hv.z, s1[4*q+2], si); sj = fmaf(hv.z, s2[4*q+2], sj);
        si = fmaf(hv.w, s1[4*q+3], si); sj = fmaf(hv.w, s2[4*q+3], sj);
    }
    g_si[g]  = si;                 g_sj[g]  = sj;
    g_eip[g] = __expf(si);         g_ejp[g] = __expf(sj);
    g_ein[g] = __expf(0.2f * si);  g_ejn[g] = __expf(0.2f * sj);
}

// ---------------- kernel 3: tensor-core aggregation ---------------------------
// 256 threads (8 warps). grid (64 i-tiles, 2 j-splits).
#define HS_STRIDE_B  528                       // 264 halves per j-row
#define WS_ROW_B     144                       // 72 halves per i-row
#define WS_HEAD_B    (64 * WS_ROW_B)           // 9216
#define OFF_HS   0
#define OFF_WS   (64 * HS_STRIDE_B)            // 33792
#define OFF_SJ   (OFF_WS + 4 * WS_HEAD_B)      // 70656
#define OFF_EJP  (OFF_SJ + 64 * 16)
#define OFF_EJN  (OFF_EJP + 64 * 16)
#define SMEM_BYTES_AGG (OFF_EJN + 64 * 16)     // 73728

__global__ void __launch_bounds__(256, 1) gat_mma(const int* __restrict__ adj) {
    extern __shared__ char sm[];
    const u32 smem_u32 = (u32)__cvta_generic_to_shared(sm);
    float4* sjS  = (float4*)(sm + OFF_SJ);
    float4* ejpS = (float4*)(sm + OFF_EJP);
    float4* ejnS = (float4*)(sm + OFF_EJN);

    const int t     = threadIdx.x;
    const int lane  = t & 31;
    const int wid   = t >> 5;
    const int i0    = blockIdx.x * TI;
    const int split = blockIdx.y;
    const int jbase0 = split * JPER;

    // Phase-A ids: one i-row, 16 consecutive j's
    const int iA = t >> 2;
    const int jg = t & 3;

    // MMA warp tiling: 4 i-warps x 2 col-warps (2 heads each)
    const int iw = (wid & 3) * 16;
    const int nb = (wid >> 2) * 128;
    const int h0 = (wid >> 2) * 2;

    const int rowL = (lane & 7) + (lane & 8);
    const int colL = (lane >> 4) << 3;

    const float4 rsi  = ((const float4*)g_si )[i0 + iA];
    const float4 reip = ((const float4*)g_eip)[i0 + iA];
    const float4 rein = ((const float4*)g_ein)[i0 + iA];

    float acc[16][4];
    #pragma unroll
    for (int q = 0; q < 16; q++)
        #pragma unroll
        for (int r = 0; r < 4; r++) acc[q][r] = 0.f;
    float Zloc[4] = {0.f, 0.f, 0.f, 0.f};

    for (int c = 0; c < NCHUNK; c++) {
        const int jb = jbase0 + c * JC;
        __syncthreads();

        if (t < 64) {
            sjS [t] = ((const float4*)g_sj )[jb + t];
            ejpS[t] = ((const float4*)g_ejp)[jb + t];
            ejnS[t] = ((const float4*)g_ejn)[jb + t];
        }
        {
            const int4* src = (const int4*)(g_hh + (size_t)jb * HD);
            #pragma unroll
            for (int r = 0; r < 8; r++) {
                int v = r * 256 + t;
                int4 val = src[v];
                int j = v >> 5, col16 = v & 31;
                *(int4*)(sm + OFF_HS + j * HS_STRIDE_B + col16 * 16) = val;
            }
        }
        __syncthreads();

        // Phase A: fp16 weight tile wS[h][i][j]
        {
            const int* arow = adj + (size_t)(i0 + iA) * NN + jb + jg * 16;
            int avv[16];
            #pragma unroll
            for (int k = 0; k < 4; k++) {
                int4 a4 = ((const int4*)arow)[k];
                avv[4*k+0] = a4.x; avv[4*k+1] = a4.y; avv[4*k+2] = a4.z; avv[4*k+3] = a4.w;
            }
            u32 ph[4][8];
            #pragma unroll
            for (int p = 0; p < 8; p++) {
                const int j0 = jg * 16 + 2 * p;
                const float e0 = (float)avv[2*p];
                const float e1 = (float)avv[2*p+1];
                float4 sjA = sjS[j0],  sjB = sjS[j0+1];
                float4 epA = ejpS[j0], epB = ejpS[j0+1];
                float4 enA = ejnS[j0], enB = ejnS[j0+1];
                float w0, w1;
                w0 = ((rsi.x + sjA.x >= 0.f) ? reip.x*epA.x : rein.x*enA.x) * e0;
                w1 = ((rsi.x + sjB.x >= 0.f) ? reip.x*epB.x : rein.x*enB.x) * e1;
                Zloc[0] += w0 + w1; ph[0][p] = h2_u32(__floats2half2_rn(w0, w1));
                w0 = ((rsi.y + sjA.y >= 0.f) ? reip.y*epA.y : rein.y*enA.y) * e0;
                w1 = ((rsi.y + sjB.y >= 0.f) ? reip.y*epB.y : rein.y*enB.y) * e1;
                Zloc[1] += w0 + w1; ph[1][p] = h2_u32(__floats2half2_rn(w0, w1));
                w0 = ((rsi.z + sjA.z >= 0.f) ? reip.z*epA.z : rein.z*enA.z) * e0;
                w1 = ((rsi.z + sjB.z >= 0.f) ? reip.z*epB.z : rein.z*enB.z) * e1;
                Zloc[2] += w0 + w1; ph[2][p] = h2_u32(__floats2half2_rn(w0, w1));
                w0 = ((rsi.w + sjA.w >= 0.f) ? reip.w*epA.w : rein.w*enA.w) * e0;
                w1 = ((rsi.w + sjB.w >= 0.f) ? reip.w*epB.w : rein.w*enB.w) * e1;
                Zloc[3] += w0 + w1; ph[3][p] = h2_u32(__floats2half2_rn(w0, w1));
            }
            #pragma unroll
            for (int hh = 0; hh < 4; hh++) {
                char* dst = sm + OFF_WS + hh * WS_HEAD_B + iA * WS_ROW_B + jg * 32;
                *(int4*)dst        = make_int4(ph[hh][0], ph[hh][1], ph[hh][2], ph[hh][3]);
                *(int4*)(dst + 16) = make_int4(ph[hh][4], ph[hh][5], ph[hh][6], ph[hh][7]);
            }
        }
        __syncthreads();

        // Phase B: MMA
        #pragma unroll
        for (int ks = 0; ks < 4; ks++) {
            u32 A0[4], A1[4];
            u32 aAddr0 = smem_u32 + OFF_WS + (h0    ) * WS_HEAD_B
                       + (iw + rowL) * WS_ROW_B + (ks * 16 + colL) * 2;
            u32 aAddr1 = aAddr0 + WS_HEAD_B;
            ldsm_x4(A0[0], A0[1], A0[2], A0[3], aAddr0);
            ldsm_x4(A1[0], A1[1], A1[2], A1[3], aAddr1);
            #pragma unroll
            for (int p = 0; p < 8; p++) {
                u32 b0, b1, b2, b3;
                u32 bAddr = smem_u32 + OFF_HS + (ks * 16 + rowL) * HS_STRIDE_B
                          + (nb + p * 16 + colL) * 2;
                ldsm_x4_t(b0, b1, b2, b3, bAddr);
                u32* A = (p < 4) ? A0 : A1;
                mma16816(acc[2*p],   A[0], A[1], A[2], A[3], b0, b1);
                mma16816(acc[2*p+1], A[0], A[1], A[2], A[3], b2, b3);
            }
        }
    }

    // writeback partials
    {
        float* base = g_part + (size_t)split * NN * HD;
        const int r0 = i0 + iw + (lane >> 2);
        const int cc = (lane & 3) * 2;
        #pragma unroll
        for (int q = 0; q < 16; q++) {
            const int col = nb + q * 8 + cc;
            *(float2*)&base[(size_t)(r0    ) * HD + col] = make_float2(acc[q][0], acc[q][1]);
            *(float2*)&base[(size_t)(r0 + 8) * HD + col] = make_float2(acc[q][2], acc[q][3]);
        }
    }
    // Z reduce over jg (4 lanes) and writeback
    #pragma unroll
    for (int hh = 0; hh < 4; hh++) {
        Zloc[hh] += __shfl_xor_sync(0xffffffffu, Zloc[hh], 1);
        Zloc[hh] += __shfl_xor_sync(0xffffffffu, Zloc[hh], 2);
    }
    if (jg == 0) {
        float4 z4 = make_float4(Zloc[0], Zloc[1], Zloc[2], Zloc[3]);
        ((float4*)(g_Z + (size_t)split * NN * Hh))[i0 + iA] = z4;
    }
}

// ---------------- kernel 4: combine splits + normalize -----------------------
__global__ void __launch_bounds__(256) epilogue_k(float* __restrict__ out) {
    int e = blockIdx.x * 256 + threadIdx.x;
    float p = g_part[e] + g_part[(size_t)NN * HD + e];
    int i = e >> 8;
    int head = (e & 255) >> 6;
    float z = g_Z[i * Hh + head] + g_Z[(size_t)NN * Hh + i * Hh + head];
    out[e] = p / z;
}

// ---------------- launch ------------------------------------------------------
extern "C" void kernel_launch(void* const* d_in, const int* in_sizes, int n_in,
                              void* d_out, int out_size) {
    const float* x   = (const float*)d_in[0];
    const int*   adj = (const int*)  d_in[1];
    const float* W   = (const float*)d_in[2];
    const float* a1  = (const float*)d_in[3];
    const float* a2  = (const float*)d_in[4];
    float* out = (float*)d_out;

    cudaFuncSetAttribute(gat_mma, cudaFuncAttributeMaxDynamicSharedMemorySize,
                         SMEM_BYTES_AGG);

    gemm_xw  <<<dim3(HD/64, NN/64), 256>>>(x, W);
    scores_k <<<(NN*Hh)/256, 256>>>(a1, a2);
    gat_mma  <<<dim3(NN/TI, JSPLIT), 256, SMEM_BYTES_AGG>>>(adj);
    epilogue_k<<<(NN*HD)/256, 256>>>(out);
}

// round 6
// speedup vs baseline: 4.9465x; 1.5704x over previous
#include <cuda_runtime.h>
#include <cuda_fp16.h>
#include <cstdint>

// Problem constants
#define NN   4096
#define INF  256
#define Hh   4
#define Dd   64
#define HD   256         // Hh*Dd
#define TI   64          // i-rows per CTA in aggregation
#define JC   64          // j-chunk for MMA kernel
#define JSPLIT 2
#define JPER (NN/JSPLIT) // 2048
#define NCHUNK (JPER/JC) // 32

using u64 = unsigned long long;
using u32 = unsigned int;

// ---------------- device scratch ---------------------------------------------
__device__ float  g_h [NN*HD];            // fp32 h = x@W (for scores)
__device__ __half g_hh[NN*HD];            // fp16 copy (MMA B operand)
__device__ float g_si[NN*Hh];
__device__ float g_sj[NN*Hh];
__device__ float g_eip[NN*Hh];            // exp(si-2)
__device__ float g_ein[NN*Hh];            // exp(0.2*si-2)
__device__ float g_ejp[NN*Hh];            // exp(sj-2)
__device__ float g_ejn[NN*Hh];            // exp(0.2*sj-2)
__device__ u32   g_tab2[(NN/2)*12];       // packed half2 tables [np][h*3+{sj,ejp,ejn}]
__device__ float g_part[JSPLIT*NN*HD];    // partial accumulators
__device__ float g_Z[JSPLIT*NN*Hh];       // partial normalizers

// ---------------- packed helpers ----------------------------------------------
__device__ __forceinline__ u64 pack2(float x, float y) {
    u64 r; asm("mov.b64 %0, {%1,%2};" : "=l"(r) : "f"(x), "f"(y)); return r;
}
__device__ __forceinline__ float2 unpack2(u64 v) {
    float2 r; asm("mov.b64 {%0,%1}, %2;" : "=f"(r.x), "=f"(r.y) : "l"(v)); return r;
}
__device__ __forceinline__ u64 fma2(u64 a, u64 b, u64 c) {
    u64 d; asm("fma.rn.f32x2 %0, %1, %2, %3;" : "=l"(d) : "l"(a), "l"(b), "l"(c));
    return d;
}
__device__ __forceinline__ u32 h2_u32(__half2 v) {
    __half2_raw r = *(__half2_raw*)&v;
    return (u32)r.x | ((u32)r.y << 16);
}
__device__ __forceinline__ __half2 u32_h2(u32 v) {
    __half2_raw r; r.x = (unsigned short)(v & 0xFFFFu); r.y = (unsigned short)(v >> 16);
    return *(__half2*)&r;
}

// ---------------- mma / ldmatrix helpers --------------------------------------
__device__ __forceinline__ void ldsm_x4(u32& r0, u32& r1, u32& r2, u32& r3, u32 addr) {
    asm volatile("ldmatrix.sync.aligned.m8n8.x4.shared.b16 {%0,%1,%2,%3}, [%4];"
                 : "=r"(r0), "=r"(r1), "=r"(r2), "=r"(r3) : "r"(addr));
}
__device__ __forceinline__ void ldsm_x4_t(u32& r0, u32& r1, u32& r2, u32& r3, u32 addr) {
    asm volatile("ldmatrix.sync.aligned.m8n8.x4.trans.shared.b16 {%0,%1,%2,%3}, [%4];"
                 : "=r"(r0), "=r"(r1), "=r"(r2), "=r"(r3) : "r"(addr));
}
__device__ __forceinline__ void ldsm_x2_t(u32& r0, u32& r1, u32 addr) {
    asm volatile("ldmatrix.sync.aligned.m8n8.x2.trans.shared.b16 {%0,%1}, [%2];"
                 : "=r"(r0), "=r"(r1) : "r"(addr));
}
__device__ __forceinline__ void mma16816(float* c, u32 a0, u32 a1, u32 a2, u32 a3,
                                         u32 b0, u32 b1) {
    asm volatile("mma.sync.aligned.m16n8k16.row.col.f32.f16.f16.f32 "
                 "{%0,%1,%2,%3},{%4,%5,%6,%7},{%8,%9},{%0,%1,%2,%3};"
                 : "+f"(c[0]), "+f"(c[1]), "+f"(c[2]), "+f"(c[3])
                 : "r"(a0), "r"(a1), "r"(a2), "r"(a3), "r"(b0), "r"(b1));
}

// ---------------- kernel 1: h = x @ W  (also writes fp16 copy) ----------------
__global__ void __launch_bounds__(256) gemm_xw(const float* __restrict__ x,
                                               const float* __restrict__ W) {
    __shared__ float As[16*64];   // [k][m]
    __shared__ float Bs[16*64];   // [k][n]
    const int t = threadIdx.x;
    const int row0 = blockIdx.y * 64;
    const int col0 = blockIdx.x * 64;
    const int tx = t & 15;
    const int ty = t >> 4;

    u64 acc[2][4];
    #pragma unroll
    for (int m = 0; m < 2; m++)
        #pragma unroll
        for (int n = 0; n < 4; n++) acc[m][n] = 0ull;

    for (int kb = 0; kb < INF; kb += 16) {
        {
            const int aRow = t >> 2;
            const int aK4  = (t & 3) * 4;
            float4 av = *(const float4*)(x + (size_t)(row0 + aRow) * INF + kb + aK4);
            As[(aK4 + 0) * 64 + aRow] = av.x;
            As[(aK4 + 1) * 64 + aRow] = av.y;
            As[(aK4 + 2) * 64 + aRow] = av.z;
            As[(aK4 + 3) * 64 + aRow] = av.w;
        }
        {
            const int bK  = t >> 4;
            const int bN4 = (t & 15) * 4;
            *(float4*)&Bs[bK * 64 + bN4] =
                *(const float4*)(W + (size_t)(kb + bK) * HD + col0 + bN4);
        }
        __syncthreads();
        #pragma unroll
        for (int k = 0; k < 16; k++) {
            float4 a4 = *(const float4*)&As[k * 64 + ty * 4];
            float4 b4 = *(const float4*)&Bs[k * 64 + tx * 4];
            u64 a01 = pack2(a4.x, a4.y);
            u64 a23 = pack2(a4.z, a4.w);
            u64 bb0 = pack2(b4.x, b4.x), bb1 = pack2(b4.y, b4.y);
            u64 bb2 = pack2(b4.z, b4.z), bb3 = pack2(b4.w, b4.w);
            acc[0][0] = fma2(a01, bb0, acc[0][0]); acc[1][0] = fma2(a23, bb0, acc[1][0]);
            acc[0][1] = fma2(a01, bb1, acc[0][1]); acc[1][1] = fma2(a23, bb1, acc[1][1]);
            acc[0][2] = fma2(a01, bb2, acc[0][2]); acc[1][2] = fma2(a23, bb2, acc[1][2]);
            acc[0][3] = fma2(a01, bb3, acc[0][3]); acc[1][3] = fma2(a23, bb3, acc[1][3]);
        }
        __syncthreads();
    }
    #pragma unroll
    for (int mp = 0; mp < 2; mp++) {
        float2 v[4];
        #pragma unroll
        for (int n = 0; n < 4; n++) v[n] = unpack2(acc[mp][n]);
        int r0 = row0 + ty * 4 + mp * 2;
        int c0 = col0 + tx * 4;
        #pragma unroll
        for (int n = 0; n < 4; n++) {
            g_h[(size_t)(r0 + 0) * HD + c0 + n] = v[n].x;
            g_h[(size_t)(r0 + 1) * HD + c0 + n] = v[n].y;
        }
        __half2 hx0 = __floats2half2_rn(v[0].x, v[1].x);
        __half2 hx1 = __floats2half2_rn(v[2].x, v[3].x);
        __half2 hy0 = __floats2half2_rn(v[0].y, v[1].y);
        __half2 hy1 = __floats2half2_rn(v[2].y, v[3].y);
        *(__half2*)&g_hh[(size_t)(r0 + 0) * HD + c0]     = hx0;
        *(__half2*)&g_hh[(size_t)(r0 + 0) * HD + c0 + 2] = hx1;
        *(__half2*)&g_hh[(size_t)(r0 + 1) * HD + c0]     = hy0;
        *(__half2*)&g_hh[(size_t)(r0 + 1) * HD + c0 + 2] = hy1;
    }
}

// ---------------- kernel 2: scores + shifted exp tables -----------------------
__global__ void __launch_bounds__(256) scores_k(const float* __restrict__ a1,
                                                const float* __restrict__ a2) {
    __shared__ float s1[Dd], s2[Dd];
    if (threadIdx.x < Dd)            s1[threadIdx.x]      = a1[threadIdx.x];
    else if (threadIdx.x < 2 * Dd)   s2[threadIdx.x - Dd] = a2[threadIdx.x - Dd];
    __syncthreads();

    const int g  = blockIdx.x * 256 + threadIdx.x;
    const int n  = g >> 2;
    const int hh = g & 3;
    const float* hrow = g_h + (size_t)n * HD + hh * Dd;
    float si = 0.f, sj = 0.f;
    #pragma unroll
    for (int q = 0; q < 16; q++) {
        float4 hv = ((const float4*)hrow)[q];
        si = fmaf(hv.x, s1[4*q+0], si); sj = fmaf(hv.x, s2[4*q+0], sj);
        si = fmaf(hv.y, s1[4*q+1], si); sj = fmaf(hv.y, s2[4*q+1], sj);
        si = fmaf(hv.z, s1[4*q+2], si); sj = fmaf(hv.z, s2[4*q+2], sj);
        si = fmaf(hv.w, s1[4*q+3], si); sj = fmaf(hv.w, s2[4*q+3], sj);
    }
    // shift each factor by e^-2 (uniform e^-4 on weights; cancels in softmax)
    g_si[g]  = si;                     g_sj[g]  = sj;
    g_eip[g] = __expf(si - 2.f);       g_ejp[g] = __expf(sj - 2.f);
    g_ein[g] = __expf(0.2f*si - 2.f);  g_ejn[g] = __expf(0.2f*sj - 2.f);
}

// ---------------- kernel 2b: pack j-side tables as half2 pairs ----------------
__global__ void __launch_bounds__(256) tab_pack() {
    const int g  = blockIdx.x * 256 + threadIdx.x;   // 0 .. NN/2*Hh-1
    const int np = g >> 2;
    const int hh = g & 3;
    const int na = 2 * np, nb = 2 * np + 1;
    u32 s  = h2_u32(__floats2half2_rn(g_sj [na*Hh+hh], g_sj [nb*Hh+hh]));
    u32 ep = h2_u32(__floats2half2_rn(g_ejp[na*Hh+hh], g_ejp[nb*Hh+hh]));
    u32 en = h2_u32(__floats2half2_rn(g_ejn[na*Hh+hh], g_ejn[nb*Hh+hh]));
    g_tab2[np*12 + hh*3 + 0] = s;
    g_tab2[np*12 + hh*3 + 1] = ep;
    g_tab2[np*12 + hh*3 + 2] = en;
}

// ---------------- kernel 3: tensor-core aggregation ---------------------------
// 512 threads (16 warps). grid (64 i-tiles, 2 j-splits).
#define HS_STRIDE_B  528                       // 264 halves: 256 data + 8 pad (ones col @256)
#define WS_ROW_B     144                       // 72 halves per i-row
#define WS_HEAD_B    (64 * WS_ROW_B)           // 9216
#define OFF_HS   0
#define OFF_WS   (64 * HS_STRIDE_B)            // 33792
#define OFF_TAB  (OFF_WS + 4 * WS_HEAD_B)      // 70656
#define SMEM_BYTES_AGG (OFF_TAB + 32 * 48)     // 72192

__global__ void __launch_bounds__(512, 1) gat_mma(const int* __restrict__ adj) {
    extern __shared__ char sm[];
    const u32 smem_u32 = (u32)__cvta_generic_to_shared(sm);

    const int t     = threadIdx.x;
    const int lane  = t & 31;
    const int wid   = t >> 5;
    const int i0    = blockIdx.x * TI;
    const int split = blockIdx.y;
    const int jbase0 = split * JPER;

    // Phase-A ids: warp-pairs cover 64 i; wj selects 4 j-pairs (8 j), broadcast in warp
    const int iP = ((wid & 1) << 5) + lane;    // 0..63
    const int wj = wid >> 1;                   // 0..7

    // MMA warp tiling: 4 i-warps x 4 head-warps
    const int iw = (wid & 3) * 16;
    const int cw = wid >> 2;                   // head 0..3
    const int nb = cw * 64;

    const int rowL = (lane & 7) + (lane & 8);
    const int colL = (lane >> 4) << 3;

    // hoisted per-i constants as duplicated half2
    __half2 rsi2[4], rep2[4], ren2[4];
    #pragma unroll
    for (int hh = 0; hh < 4; hh++) {
        rsi2[hh] = __float2half2_rn(g_si [(size_t)(i0 + iP) * Hh + hh]);
        rep2[hh] = __float2half2_rn(g_eip[(size_t)(i0 + iP) * Hh + hh]);
        ren2[hh] = __float2half2_rn(g_ein[(size_t)(i0 + iP) * Hh + hh]);
    }
    const __half2 hz = __float2half2_rn(0.f);

    float acc[8][4];
    #pragma unroll
    for (int q = 0; q < 8; q++)
        #pragma unroll
        for (int r = 0; r < 4; r++) acc[q][r] = 0.f;
    float zacc[4] = {0.f, 0.f, 0.f, 0.f};

    for (int c = 0; c < NCHUNK; c++) {
        const int jb = jbase0 + c * JC;
        __syncthreads();

        // stage packed tables (96 int4) and ones-pad (64 rows)
        if (t < 96)
            ((int4*)(sm + OFF_TAB))[t] = ((const int4*)(g_tab2 + (size_t)(jb >> 1) * 12))[t];
        else if (t < 160) {
            int j = t - 96;
            *(int4*)(sm + OFF_HS + j * HS_STRIDE_B + 512) = make_int4(0x3C00, 0, 0, 0);
        }
        // stage h tile (2048 int4)
        {
            const int4* src = (const int4*)(g_hh + (size_t)jb * HD);
            #pragma unroll
            for (int r = 0; r < 4; r++) {
                int v = r * 512 + t;
                int4 val = src[v];
                int j = v >> 5, col16 = v & 31;
                *(int4*)(sm + OFF_HS + j * HS_STRIDE_B + col16 * 16) = val;
            }
        }
        __syncthreads();

        // Phase A: half2 weight tile wS[h][i][j]
        {
            const int* arow = adj + (size_t)(i0 + iP) * NN + jb + wj * 8;
            int4 a0 = ((const int4*)arow)[0];
            int4 a1 = ((const int4*)arow)[1];
            int avv[8] = {a0.x, a0.y, a0.z, a0.w, a1.x, a1.y, a1.z, a1.w};
            u32 ph[4][4];
            #pragma unroll
            for (int p = 0; p < 4; p++) {
                const int jpl = wj * 4 + p;
                const int4* tp = (const int4*)(sm + OFF_TAB + jpl * 48);
                int4 q0 = tp[0], q1 = tp[1], q2 = tp[2];
                u32 tw[12] = {(u32)q0.x,(u32)q0.y,(u32)q0.z,(u32)q0.w,
                              (u32)q1.x,(u32)q1.y,(u32)q1.z,(u32)q1.w,
                              (u32)q2.x,(u32)q2.y,(u32)q2.z,(u32)q2.w};
                __half2 em2 = __floats2half2_rn((float)avv[2*p], (float)avv[2*p+1]);
                #pragma unroll
                for (int hh = 0; hh < 4; hh++) {
                    __half2 sj2  = u32_h2(tw[hh*3+0]);
                    __half2 ejp2 = u32_h2(tw[hh*3+1]);
                    __half2 ejn2 = u32_h2(tw[hh*3+2]);
                    __half2 t2 = __hadd2(rsi2[hh], sj2);
                    __half2 p2 = __hmul2(rep2[hh], ejp2);
                    __half2 n2 = __hmul2(ren2[hh], ejn2);
                    __half2 m2 = __hge2(t2, hz);
                    __half2 w2 = __hfma2(m2, __hsub2(p2, n2), n2);
                    w2 = __hmul2(w2, em2);
                    ph[hh][p] = h2_u32(w2);
                }
            }
            #pragma unroll
            for (int hh = 0; hh < 4; hh++) {
                *(int4*)(sm + OFF_WS + hh * WS_HEAD_B + iP * WS_ROW_B + wj * 16) =
                    make_int4(ph[hh][0], ph[hh][1], ph[hh][2], ph[hh][3]);
            }
        }
        __syncthreads();

        // Phase B: MMA (per warp: head cw, i-rows iw..iw+15)
        #pragma unroll
        for (int ks = 0; ks < 4; ks++) {
            u32 A0, A1, A2, A3;
            u32 aAddr = smem_u32 + OFF_WS + cw * WS_HEAD_B
                      + (iw + rowL) * WS_ROW_B + (ks * 16 + colL) * 2;
            ldsm_x4(A0, A1, A2, A3, aAddr);
            // Z: ones column at byte 512
            u32 bo0, bo1;
            ldsm_x2_t(bo0, bo1, smem_u32 + OFF_HS + (ks * 16 + rowL) * HS_STRIDE_B + 512);
            mma16816(zacc, A0, A1, A2, A3, bo0, bo1);
            #pragma unroll
            for (int p = 0; p < 4; p++) {
                u32 b0, b1, b2, b3;
                u32 bAddr = smem_u32 + OFF_HS + (ks * 16 + rowL) * HS_STRIDE_B
                          + (nb + p * 16 + colL) * 2;
                ldsm_x4_t(b0, b1, b2, b3, bAddr);
                mma16816(acc[2*p],   A0, A1, A2, A3, b0, b1);
                mma16816(acc[2*p+1], A0, A1, A2, A3, b2, b3);
            }
        }
    }

    // writeback partials
    {
        float* base = g_part + (size_t)split * NN * HD;
        const int r0 = i0 + iw + (lane >> 2);
        const int cc = (lane & 3) * 2;
        #pragma unroll
        for (int q = 0; q < 8; q++) {
            const int col = nb + q * 8 + cc;
            *(float2*)&base[(size_t)(r0    ) * HD + col] = make_float2(acc[q][0], acc[q][1]);
            *(float2*)&base[(size_t)(r0 + 8) * HD + col] = make_float2(acc[q][2], acc[q][3]);
        }
    }
    // Z writeback (col 256 lives at cc==0, regs 0/2)
    if ((lane & 3) == 0) {
        const int r0 = i0 + iw + (lane >> 2);
        float* zb = g_Z + (size_t)split * NN * Hh;
        zb[(size_t)(r0    ) * Hh + cw] = zacc[0];
        zb[(size_t)(r0 + 8) * Hh + cw] = zacc[2];
    }
}

// ---------------- kernel 4: combine splits + normalize -----------------------
__global__ void __launch_bounds__(256) epilogue_k(float* __restrict__ out) {
    int e = blockIdx.x * 256 + threadIdx.x;
    float p = g_part[e] + g_part[(size_t)NN * HD + e];
    int i = e >> 8;
    int head = (e & 255) >> 6;
    float z = g_Z[i * Hh + head] + g_Z[(size_t)NN * Hh + i * Hh + head];
    out[e] = p / z;
}

// ---------------- launch ------------------------------------------------------
extern "C" void kernel_launch(void* const* d_in, const int* in_sizes, int n_in,
                              void* d_out, int out_size) {
    const float* x   = (const float*)d_in[0];
    const int*   adj = (const int*)  d_in[1];
    const float* W   = (const float*)d_in[2];
    const float* a1  = (const float*)d_in[3];
    const float* a2  = (const float*)d_in[4];
    float* out = (float*)d_out;

    cudaFuncSetAttribute(gat_mma, cudaFuncAttributeMaxDynamicSharedMemorySize,
                         SMEM_BYTES_AGG);

    gemm_xw  <<<dim3(HD/64, NN/64), 256>>>(x, W);
    scores_k <<<(NN*Hh)/256, 256>>>(a1, a2);
    tab_pack <<<(NN/2*Hh)/256, 256>>>();
    gat_mma  <<<dim3(NN/TI, JSPLIT), 512, SMEM_BYTES_AGG>>>(adj);
    epilogue_k<<<(NN*HD)/256, 256>>>(out);
}

// round 7
// speedup vs baseline: 5.3929x; 1.0902x over previous
#include <cuda_runtime.h>
#include <cuda_fp16.h>
#include <cstdint>

// Problem constants
#define NN   4096
#define INF  256
#define Hh   4
#define Dd   64
#define HD   256         // Hh*Dd
#define TI   64          // i-rows per CTA in aggregation
#define JC   64          // j-chunk for MMA kernel
#define JSPLIT 2
#define JPER (NN/JSPLIT) // 2048
#define NCHUNK (JPER/JC) // 32

using u64 = unsigned long long;
using u32 = unsigned int;

// ---------------- device scratch ---------------------------------------------
__device__ float  g_h [NN*HD];            // fp32 h = x@W (for scores)
__device__ __half g_hh[NN*HD];            // fp16 copy (MMA B operand)
__device__ float g_si[NN*Hh];
__device__ float g_sj[NN*Hh];
__device__ float g_eip[NN*Hh];            // exp(si-2)
__device__ float g_ein[NN*Hh];            // exp(0.2*si-2)
__device__ float g_ejp[NN*Hh];            // exp(sj-2)
__device__ float g_ejn[NN*Hh];            // exp(0.2*sj-2)
// SoA tables per 64-j chunk: [chunk][h][comp(sj,ejp,ejn)][jp 0..31] u32(half2)
__device__ u32   g_tab2[(NN/64)*384];
__device__ float g_part[JSPLIT*NN*HD];    // partial accumulators
__device__ float g_Z[JSPLIT*NN*Hh];       // partial normalizers

// ---------------- packed helpers ----------------------------------------------
__device__ __forceinline__ u64 pack2(float x, float y) {
    u64 r; asm("mov.b64 %0, {%1,%2};" : "=l"(r) : "f"(x), "f"(y)); return r;
}
__device__ __forceinline__ float2 unpack2(u64 v) {
    float2 r; asm("mov.b64 {%0,%1}, %2;" : "=f"(r.x), "=f"(r.y) : "l"(v)); return r;
}
__device__ __forceinline__ u64 fma2(u64 a, u64 b, u64 c) {
    u64 d; asm("fma.rn.f32x2 %0, %1, %2, %3;" : "=l"(d) : "l"(a), "l"(b), "l"(c));
    return d;
}
__device__ __forceinline__ u32 h2_u32(__half2 v) {
    __half2_raw r = *(__half2_raw*)&v;
    return (u32)r.x | ((u32)r.y << 16);
}
__device__ __forceinline__ __half2 u32_h2(u32 v) {
    __half2_raw r; r.x = (unsigned short)(v & 0xFFFFu); r.y = (unsigned short)(v >> 16);
    return *(__half2*)&r;
}

// ---------------- cp.async helpers ---------------------------------------------
__device__ __forceinline__ void cp_async16(u32 dst, const void* src) {
    asm volatile("cp.async.cg.shared.global [%0], [%1], 16;" :: "r"(dst), "l"(src));
}
__device__ __forceinline__ void cp_commit() { asm volatile("cp.async.commit_group;"); }
__device__ __forceinline__ void cp_wait0()  { asm volatile("cp.async.wait_group 0;" ::: "memory"); }

// ---------------- mma / ldmatrix helpers --------------------------------------
__device__ __forceinline__ void ldsm_x4(u32& r0, u32& r1, u32& r2, u32& r3, u32 addr) {
    asm volatile("ldmatrix.sync.aligned.m8n8.x4.shared.b16 {%0,%1,%2,%3}, [%4];"
                 : "=r"(r0), "=r"(r1), "=r"(r2), "=r"(r3) : "r"(addr));
}
__device__ __forceinline__ void ldsm_x4_t(u32& r0, u32& r1, u32& r2, u32& r3, u32 addr) {
    asm volatile("ldmatrix.sync.aligned.m8n8.x4.trans.shared.b16 {%0,%1,%2,%3}, [%4];"
                 : "=r"(r0), "=r"(r1), "=r"(r2), "=r"(r3) : "r"(addr));
}
__device__ __forceinline__ void ldsm_x2_t(u32& r0, u32& r1, u32 addr) {
    asm volatile("ldmatrix.sync.aligned.m8n8.x2.trans.shared.b16 {%0,%1}, [%2];"
                 : "=r"(r0), "=r"(r1) : "r"(addr));
}
__device__ __forceinline__ void mma16816(float* c, u32 a0, u32 a1, u32 a2, u32 a3,
                                         u32 b0, u32 b1) {
    asm volatile("mma.sync.aligned.m16n8k16.row.col.f32.f16.f16.f32 "
                 "{%0,%1,%2,%3},{%4,%5,%6,%7},{%8,%9},{%0,%1,%2,%3};"
                 : "+f"(c[0]), "+f"(c[1]), "+f"(c[2]), "+f"(c[3])
                 : "r"(a0), "r"(a1), "r"(a2), "r"(a3), "r"(b0), "r"(b1));
}

// ---------------- kernel 1: h = x @ W  (also writes fp16 copy) ----------------
__global__ void __launch_bounds__(256) gemm_xw(const float* __restrict__ x,
                                               const float* __restrict__ W) {
    __shared__ float As[16*64];   // [k][m]
    __shared__ float Bs[16*64];   // [k][n]
    const int t = threadIdx.x;
    const int row0 = blockIdx.y * 64;
    const int col0 = blockIdx.x * 64;
    const int tx = t & 15;
    const int ty = t >> 4;

    u64 acc[2][4];
    #pragma unroll
    for (int m = 0; m < 2; m++)
        #pragma unroll
        for (int n = 0; n < 4; n++) acc[m][n] = 0ull;

    for (int kb = 0; kb < INF; kb += 16) {
        {
            const int aRow = t >> 2;
            const int aK4  = (t & 3) * 4;
            float4 av = *(const float4*)(x + (size_t)(row0 + aRow) * INF + kb + aK4);
            As[(aK4 + 0) * 64 + aRow] = av.x;
            As[(aK4 + 1) * 64 + aRow] = av.y;
            As[(aK4 + 2) * 64 + aRow] = av.z;
            As[(aK4 + 3) * 64 + aRow] = av.w;
        }
        {
            const int bK  = t >> 4;
            const int bN4 = (t & 15) * 4;
            *(float4*)&Bs[bK * 64 + bN4] =
                *(const float4*)(W + (size_t)(kb + bK) * HD + col0 + bN4);
        }
        __syncthreads();
        #pragma unroll
        for (int k = 0; k < 16; k++) {
            float4 a4 = *(const float4*)&As[k * 64 + ty * 4];
            float4 b4 = *(const float4*)&Bs[k * 64 + tx * 4];
            u64 a01 = pack2(a4.x, a4.y);
            u64 a23 = pack2(a4.z, a4.w);
            u64 bb0 = pack2(b4.x, b4.x), bb1 = pack2(b4.y, b4.y);
            u64 bb2 = pack2(b4.z, b4.z), bb3 = pack2(b4.w, b4.w);
            acc[0][0] = fma2(a01, bb0, acc[0][0]); acc[1][0] = fma2(a23, bb0, acc[1][0]);
            acc[0][1] = fma2(a01, bb1, acc[0][1]); acc[1][1] = fma2(a23, bb1, acc[1][1]);
            acc[0][2] = fma2(a01, bb2, acc[0][2]); acc[1][2] = fma2(a23, bb2, acc[1][2]);
            acc[0][3] = fma2(a01, bb3, acc[0][3]); acc[1][3] = fma2(a23, bb3, acc[1][3]);
        }
        __syncthreads();
    }
    #pragma unroll
    for (int mp = 0; mp < 2; mp++) {
        float2 v[4];
        #pragma unroll
        for (int n = 0; n < 4; n++) v[n] = unpack2(acc[mp][n]);
        int r0 = row0 + ty * 4 + mp * 2;
        int c0 = col0 + tx * 4;
        #pragma unroll
        for (int n = 0; n < 4; n++) {
            g_h[(size_t)(r0 + 0) * HD + c0 + n] = v[n].x;
            g_h[(size_t)(r0 + 1) * HD + c0 + n] = v[n].y;
        }
        __half2 hx0 = __floats2half2_rn(v[0].x, v[1].x);
        __half2 hx1 = __floats2half2_rn(v[2].x, v[3].x);
        __half2 hy0 = __floats2half2_rn(v[0].y, v[1].y);
        __half2 hy1 = __floats2half2_rn(v[2].y, v[3].y);
        *(__half2*)&g_hh[(size_t)(r0 + 0) * HD + c0]     = hx0;
        *(__half2*)&g_hh[(size_t)(r0 + 0) * HD + c0 + 2] = hx1;
        *(__half2*)&g_hh[(size_t)(r0 + 1) * HD + c0]     = hy0;
        *(__half2*)&g_hh[(size_t)(r0 + 1) * HD + c0 + 2] = hy1;
    }
}

// ---------------- kernel 2: scores + shifted exp tables -----------------------
__global__ void __launch_bounds__(256) scores_k(const float* __restrict__ a1,
                                                const float* __restrict__ a2) {
    __shared__ float s1[Dd], s2[Dd];
    if (threadIdx.x < Dd)            s1[threadIdx.x]      = a1[threadIdx.x];
    else if (threadIdx.x < 2 * Dd)   s2[threadIdx.x - Dd] = a2[threadIdx.x - Dd];
    __syncthreads();

    const int g  = blockIdx.x * 256 + threadIdx.x;
    const int n  = g >> 2;
    const int hh = g & 3;
    const float* hrow = g_h + (size_t)n * HD + hh * Dd;
    float si = 0.f, sj = 0.f;
    #pragma unroll
    for (int q = 0; q < 16; q++) {
        float4 hv = ((const float4*)hrow)[q];
        si = fmaf(hv.x, s1[4*q+0], si); sj = fmaf(hv.x, s2[4*q+0], sj);
        si = fmaf(hv.y, s1[4*q+1], si); sj = fmaf(hv.y, s2[4*q+1], sj);
        si = fmaf(hv.z, s1[4*q+2], si); sj = fmaf(hv.z, s2[4*q+2], sj);
        si = fmaf(hv.w, s1[4*q+3], si); sj = fmaf(hv.w, s2[4*q+3], sj);
    }
    g_si[g]  = si;                     g_sj[g]  = sj;
    g_eip[g] = __expf(si - 2.f);       g_ejp[g] = __expf(sj - 2.f);
    g_ein[g] = __expf(0.2f*si - 2.f);  g_ejn[g] = __expf(0.2f*sj - 2.f);
}

// ---------------- kernel 2b: pack j-side tables (SoA per 64-chunk) ------------
__global__ void __launch_bounds__(256) tab_pack() {
    const int g  = blockIdx.x * 256 + threadIdx.x;   // 0 .. NN/2*Hh-1
    const int np = g >> 2;
    const int hh = g & 3;
    const int na = 2 * np, nb = 2 * np + 1;
    u32 s  = h2_u32(__floats2half2_rn(g_sj [na*Hh+hh], g_sj [nb*Hh+hh]));
    u32 ep = h2_u32(__floats2half2_rn(g_ejp[na*Hh+hh], g_ejp[nb*Hh+hh]));
    u32 en = h2_u32(__floats2half2_rn(g_ejn[na*Hh+hh], g_ejn[nb*Hh+hh]));
    const int base = (np >> 5) * 384 + hh * 96 + (np & 31);
    g_tab2[base +  0] = s;
    g_tab2[base + 32] = ep;
    g_tab2[base + 64] = en;
}

// ---------------- kernel 3: tensor-core aggregation ---------------------------
// 512 threads (16 warps). grid (64 i-tiles, 2 j-splits).
// smem: hS x2 (double-buffered, cp.async) | wS swizzled 128B rows | tab x2
#define HS_STRIDE_B  528                       // 264 halves: 256 data + ones col @512
#define OFF_HS0  0
#define OFF_HS1  (64 * HS_STRIDE_B)            // 33792
#define OFF_WS   (2 * 64 * HS_STRIDE_B)        // 67584, 4 heads x 64 rows x 128B
#define OFF_TAB0 (OFF_WS + 4 * 64 * 128)       // 100352
#define OFF_TAB1 (OFF_TAB0 + 1536)             // 101888
#define SMEM_BYTES_AGG (OFF_TAB1 + 1536)       // 103424

__global__ void __launch_bounds__(512, 1) gat_mma(const int* __restrict__ adj) {
    extern __shared__ char sm[];
    const u32 smem_u32 = (u32)__cvta_generic_to_shared(sm);

    const int t     = threadIdx.x;
    const int lane  = t & 31;
    const int wid   = t >> 5;
    const int i0    = blockIdx.x * TI;
    const int split = blockIdx.y;
    const int jbase0 = split * JPER;

    // Phase-A ids: lane = j-pair (0..31 = whole 64-j chunk), warp owns 4 i-rows
    const int iA0 = wid * 4;

    // MMA warp tiling: 2 i-groups (32 rows) x 8 col-groups (32 cols)
    const int iw2  = (wid & 1) * 32;
    const int cw8  = wid >> 1;                 // 0..7
    const int ncol = cw8 * 32;                 // halves
    const int headA = cw8 >> 1;
    const bool doZ  = (cw8 & 1) == 0;
    const int rowL = (lane & 7) + (lane & 8);
    const int colL = (lane >> 4) << 3;

    // hoisted per-i constants (chunk-invariant): rsi dup-half2, (eip,ein) packed
    u32 rsi2[4][4], rpn[4][4];
    #pragma unroll
    for (int i = 0; i < 4; i++)
        #pragma unroll
        for (int h = 0; h < 4; h++) {
            const size_t gix = (size_t)(i0 + iA0 + i) * Hh + h;
            rsi2[i][h] = h2_u32(__float2half2_rn(g_si[gix]));
            rpn[i][h]  = h2_u32(__halves2half2(__float2half(g_eip[gix]),
                                               __float2half(g_ein[gix])));
        }
    const __half2 hz = __float2half2_rn(0.f);

    float acc[8][4];
    #pragma unroll
    for (int q = 0; q < 8; q++)
        #pragma unroll
        for (int r = 0; r < 4; r++) acc[q][r] = 0.f;
    float zacc[2][4];
    #pragma unroll
    for (int m = 0; m < 2; m++)
        #pragma unroll
        for (int r = 0; r < 4; r++) zacc[m][r] = 0.f;

    // ---- staging helper (cp.async) ----
    auto stage = [&](int c, int buf) {
        const int jb = jbase0 + c * JC;
        const u32 hbase = smem_u32 + (buf ? OFF_HS1 : OFF_HS0);
        const char* gsrc = (const char*)(g_hh + (size_t)jb * HD);
        #pragma unroll
        for (int r = 0; r < 4; r++) {
            int v = r * 512 + t;               // 0..2047 int4
            int j = v >> 5, c16 = v & 31;
            cp_async16(hbase + j * HS_STRIDE_B + c16 * 16, gsrc + (size_t)v * 16);
        }
        if (t < 96) {
            const u32 tbase = smem_u32 + (buf ? OFF_TAB1 : OFF_TAB0);
            const char* tsrc = (const char*)(g_tab2 + (size_t)(jb >> 6) * 384);
            cp_async16(tbase + t * 16, tsrc + t * 16);
        }
    };

    // prologue: ones columns (both buffers, never overwritten) + stage(0)
    if (t < 128) {
        int buf = t >> 6, j = t & 63;
        *(int4*)(sm + (buf ? OFF_HS1 : OFF_HS0) + j * HS_STRIDE_B + 512) =
            make_int4(0x3C00, 0, 0, 0);
    }
    stage(0, 0); cp_commit();
    cp_wait0();
    __syncthreads();

    for (int c = 0; c < NCHUNK; c++) {
        const int cur = c & 1;
        if (c + 1 < NCHUNK) { stage(c + 1, cur ^ 1); cp_commit(); }

        // ---- Phase A: half2 weight tile (lane=jp, loop i,h), swizzled STS.32 ----
        {
            const u32 tbase = smem_u32 + (cur ? OFF_TAB1 : OFF_TAB0);
            u32 tv[4][3];
            #pragma unroll
            for (int h = 0; h < 4; h++)
                #pragma unroll
                for (int q = 0; q < 3; q++)
                    asm volatile("ld.shared.u32 %0, [%1];"
                                 : "=r"(tv[h][q])
                                 : "r"(tbase + (u32)(h * 96 + q * 32 + lane) * 4));
            const int jb = jbase0 + c * JC;
            #pragma unroll
            for (int i = 0; i < 4; i++) {
                const int li = iA0 + i;
                int2 av = *(const int2*)(adj + (size_t)(i0 + li) * NN + jb + 2 * lane);
                __half2 em2 = __floats2half2_rn((float)av.x, (float)av.y);
                const u32 sw = ((u32)(li & 7)) << 4;
                const u32 rowbase = smem_u32 + OFF_WS + (u32)li * 128;
                #pragma unroll
                for (int h = 0; h < 4; h++) {
                    __half2 rp   = u32_h2(rpn[i][h]);
                    __half2 rep2 = __low2half2(rp);
                    __half2 ren2 = __high2half2(rp);
                    __half2 t2 = __hadd2(u32_h2(rsi2[i][h]), u32_h2(tv[h][0]));
                    __half2 p2 = __hmul2(rep2, u32_h2(tv[h][1]));
                    __half2 n2 = __hmul2(ren2, u32_h2(tv[h][2]));
                    __half2 m2 = __hge2(t2, hz);
                    __half2 w2 = __hfma2(m2, __hsub2(p2, n2), n2);
                    w2 = __hmul2(w2, em2);
                    const u32 addr = rowbase + (u32)(h * 8192) + (((u32)lane * 4) ^ sw);
                    asm volatile("st.shared.u32 [%0], %1;" :: "r"(addr), "r"(h2_u32(w2)));
                }
            }
        }
        __syncthreads();

        // ---- Phase B: MMA ----
        const u32 hbase = smem_u32 + (cur ? OFF_HS1 : OFF_HS0);
        #pragma unroll
        for (int ks = 0; ks < 4; ks++) {
            u32 A0[4], A1[4];
            {
                const int r0 = iw2 + rowL, r1 = iw2 + 16 + rowL;
                const u32 cb = (u32)(ks * 32) + ((u32)(lane >> 4) << 4);
                u32 a0a = smem_u32 + OFF_WS + (u32)(headA * 8192) + (u32)r0 * 128
                        + (cb ^ (((u32)(r0 & 7)) << 4));
                u32 a1a = smem_u32 + OFF_WS + (u32)(headA * 8192) + (u32)r1 * 128
                        + (cb ^ (((u32)(r1 & 7)) << 4));
                ldsm_x4(A0[0], A0[1], A0[2], A0[3], a0a);
                ldsm_x4(A1[0], A1[1], A1[2], A1[3], a1a);
            }
            if (doZ) {
                u32 bo0, bo1;
                ldsm_x2_t(bo0, bo1, hbase + (u32)(ks * 16 + rowL) * HS_STRIDE_B + 512);
                mma16816(zacc[0], A0[0], A0[1], A0[2], A0[3], bo0, bo1);
                mma16816(zacc[1], A1[0], A1[1], A1[2], A1[3], bo0, bo1);
            }
            #pragma unroll
            for (int p = 0; p < 2; p++) {
                u32 b0, b1, b2, b3;
                u32 ba = hbase + (u32)(ks * 16 + rowL) * HS_STRIDE_B
                       + (u32)(ncol + p * 16 + colL) * 2;
                ldsm_x4_t(b0, b1, b2, b3, ba);
                mma16816(acc[p*2 + 0], A0[0], A0[1], A0[2], A0[3], b0, b1);
                mma16816(acc[p*2 + 1], A0[0], A0[1], A0[2], A0[3], b2, b3);
                mma16816(acc[4 + p*2 + 0], A1[0], A1[1], A1[2], A1[3], b0, b1);
                mma16816(acc[4 + p*2 + 1], A1[0], A1[1], A1[2], A1[3], b2, b3);
            }
        }
        cp_wait0();          // my stage(c+1) copies landed
        __syncthreads();     // publish staging; all B(c) readers done
    }

    // ---- writeback partials ----
    {
        float* base = g_part + (size_t)split * NN * HD;
        const int cc = (lane & 3) * 2;
        #pragma unroll
        for (int m = 0; m < 2; m++) {
            const int r0 = i0 + iw2 + m * 16 + (lane >> 2);
            #pragma unroll
            for (int n = 0; n < 4; n++) {
                const int col = ncol + n * 8 + cc;
                *(float2*)&base[(size_t)(r0    ) * HD + col] =
                    make_float2(acc[m*4+n][0], acc[m*4+n][1]);
                *(float2*)&base[(size_t)(r0 + 8) * HD + col] =
                    make_float2(acc[m*4+n][2], acc[m*4+n][3]);
            }
        }
    }
    if (doZ && (lane & 3) == 0) {
        float* zb = g_Z + (size_t)split * NN * Hh;
        #pragma unroll
        for (int m = 0; m < 2; m++) {
            const int r0 = i0 + iw2 + m * 16 + (lane >> 2);
            zb[(size_t)(r0    ) * Hh + headA] = zacc[m][0];
            zb[(size_t)(r0 + 8) * Hh + headA] = zacc[m][2];
        }
    }
}

// ---------------- kernel 4: combine splits + normalize -----------------------
__global__ void __launch_bounds__(256) epilogue_k(float* __restrict__ out) {
    int e = blockIdx.x * 256 + threadIdx.x;
    float p = g_part[e] + g_part[(size_t)NN * HD + e];
    int i = e >> 8;
    int head = (e & 255) >> 6;
    float z = g_Z[i * Hh + head] + g_Z[(size_t)NN * Hh + i * Hh + head];
    out[e] = p / z;
}

// ---------------- launch ------------------------------------------------------
extern "C" void kernel_launch(void* const* d_in, const int* in_sizes, int n_in,
                              void* d_out, int out_size) {
    const float* x   = (const float*)d_in[0];
    const int*   adj = (const int*)  d_in[1];
    const float* W   = (const float*)d_in[2];
    const float* a1  = (const float*)d_in[3];
    const float* a2  = (const float*)d_in[4];
    float* out = (float*)d_out;

    cudaFuncSetAttribute(gat_mma, cudaFuncAttributeMaxDynamicSharedMemorySize,
                         SMEM_BYTES_AGG);

    gemm_xw  <<<dim3(HD/64, NN/64), 256>>>(x, W);
    scores_k <<<(NN*Hh)/256, 256>>>(a1, a2);
    tab_pack <<<(NN/2*Hh)/256, 256>>>();
    gat_mma  <<<dim3(NN/TI, JSPLIT), 512, SMEM_BYTES_AGG>>>(adj);
    epilogue_k<<<(NN*HD)/256, 256>>>(out);
}

// round 10
// speedup vs baseline: 6.8888x; 1.2774x over previous
#include <cuda_runtime.h>
#include <cuda_fp16.h>
#include <cstdint>

// Problem constants
#define NN   4096
#define INF  256
#define Hh   4
#define Dd   64
#define HD   256         // Hh*Dd
#define TI   64          // i-rows per CTA in aggregation
#define JC   64          // j-chunk for MMA kernel
#define JSPLIT 2
#define JPER (NN/JSPLIT) // 2048
#define NCHUNK (JPER/JC) // 32

using u64 = unsigned long long;
using u32 = unsigned int;

// ---------------- device scratch ---------------------------------------------
__device__ float  g_h [NN*HD];            // fp32 h = x@W (for scores)
__device__ __half g_hh[NN*HD];            // fp16 copy (MMA B operand)
__device__ float g_si[NN*Hh];
__device__ float g_sj[NN*Hh];
__device__ float g_eip[NN*Hh];            // exp(si-2)
__device__ float g_ein[NN*Hh];            // exp(0.2*si-2)
__device__ float g_ejp[NN*Hh];            // exp(sj-2)
__device__ float g_ejn[NN*Hh];            // exp(0.2*sj-2)
// SoA tables per 64-j chunk: [chunk][h][comp(sj,ejp,ejn)][jp 0..31] u32(half2)
__device__ u32   g_tab2[(NN/64)*384];
__device__ float g_part[JSPLIT*NN*HD];    // partial accumulators
__device__ float g_Z[JSPLIT*NN*Hh];       // partial normalizers

// ---------------- packed helpers ----------------------------------------------
__device__ __forceinline__ u64 pack2(float x, float y) {
    u64 r; asm("mov.b64 %0, {%1,%2};" : "=l"(r) : "f"(x), "f"(y)); return r;
}
__device__ __forceinline__ float2 unpack2(u64 v) {
    float2 r; asm("mov.b64 {%0,%1}, %2;" : "=f"(r.x), "=f"(r.y) : "l"(v)); return r;
}
__device__ __forceinline__ u64 fma2(u64 a, u64 b, u64 c) {
    u64 d; asm("fma.rn.f32x2 %0, %1, %2, %3;" : "=l"(d) : "l"(a), "l"(b), "l"(c));
    return d;
}
__device__ __forceinline__ u32 h2_u32(__half2 v) {
    __half2_raw r = *(__half2_raw*)&v;
    return (u32)r.x | ((u32)r.y << 16);
}
__device__ __forceinline__ __half2 u32_h2(u32 v) {
    __half2_raw r; r.x = (unsigned short)(v & 0xFFFFu); r.y = (unsigned short)(v >> 16);
    return *(__half2*)&r;
}

// ---------------- cp.async helpers ---------------------------------------------
__device__ __forceinline__ void cp_async16(u32 dst, const void* src) {
    asm volatile("cp.async.cg.shared.global [%0], [%1], 16;" :: "r"(dst), "l"(src));
}
__device__ __forceinline__ void cp_commit() { asm volatile("cp.async.commit_group;"); }
template<int N> __device__ __forceinline__ void cp_waitN() {
    asm volatile("cp.async.wait_group %0;" :: "n"(N) : "memory");
}

// ---------------- mma / ldmatrix helpers --------------------------------------
__device__ __forceinline__ void ldsm_x4(u32& r0, u32& r1, u32& r2, u32& r3, u32 addr) {
    asm volatile("ldmatrix.sync.aligned.m8n8.x4.shared.b16 {%0,%1,%2,%3}, [%4];"
                 : "=r"(r0), "=r"(r1), "=r"(r2), "=r"(r3) : "r"(addr));
}
__device__ __forceinline__ void ldsm_x4_t(u32& r0, u32& r1, u32& r2, u32& r3, u32 addr) {
    asm volatile("ldmatrix.sync.aligned.m8n8.x4.trans.shared.b16 {%0,%1,%2,%3}, [%4];"
                 : "=r"(r0), "=r"(r1), "=r"(r2), "=r"(r3) : "r"(addr));
}
__device__ __forceinline__ void ldsm_x2_t(u32& r0, u32& r1, u32 addr) {
    asm volatile("ldmatrix.sync.aligned.m8n8.x2.trans.shared.b16 {%0,%1}, [%2];"
                 : "=r"(r0), "=r"(r1) : "r"(addr));
}
__device__ __forceinline__ void mma16816(float* c, u32 a0, u32 a1, u32 a2, u32 a3,
                                         u32 b0, u32 b1) {
    asm volatile("mma.sync.aligned.m16n8k16.row.col.f32.f16.f16.f32 "
                 "{%0,%1,%2,%3},{%4,%5,%6,%7},{%8,%9},{%0,%1,%2,%3};"
                 : "+f"(c[0]), "+f"(c[1]), "+f"(c[2]), "+f"(c[3])
                 : "r"(a0), "r"(a1), "r"(a2), "r"(a3), "r"(b0), "r"(b1));
}

// ---------------- kernel 1: h = x @ W  (also writes fp16 copy) ----------------
__global__ void __launch_bounds__(256) gemm_xw(const float* __restrict__ x,
                                               const float* __restrict__ W) {
    __shared__ float As[16*64];   // [k][m]
    __shared__ float Bs[16*64];   // [k][n]
    const int t = threadIdx.x;
    const int row0 = blockIdx.y * 64;
    const int col0 = blockIdx.x * 64;
    const int tx = t & 15;
    const int ty = t >> 4;

    u64 acc[2][4];
    #pragma unroll
    for (int m = 0; m < 2; m++)
        #pragma unroll
        for (int n = 0; n < 4; n++) acc[m][n] = 0ull;

    for (int kb = 0; kb < INF; kb += 16) {
        {
            const int aRow = t >> 2;
            const int aK4  = (t & 3) * 4;
            float4 av = *(const float4*)(x + (size_t)(row0 + aRow) * INF + kb + aK4);
            As[(aK4 + 0) * 64 + aRow] = av.x;
            As[(aK4 + 1) * 64 + aRow] = av.y;
            As[(aK4 + 2) * 64 + aRow] = av.z;
            As[(aK4 + 3) * 64 + aRow] = av.w;
        }
        {
            const int bK  = t >> 4;
            const int bN4 = (t & 15) * 4;
            *(float4*)&Bs[bK * 64 + bN4] =
                *(const float4*)(W + (size_t)(kb + bK) * HD + col0 + bN4);
        }
        __syncthreads();
        #pragma unroll
        for (int k = 0; k < 16; k++) {
            float4 a4 = *(const float4*)&As[k * 64 + ty * 4];
            float4 b4 = *(const float4*)&Bs[k * 64 + tx * 4];
            u64 a01 = pack2(a4.x, a4.y);
            u64 a23 = pack2(a4.z, a4.w);
            u64 bb0 = pack2(b4.x, b4.x), bb1 = pack2(b4.y, b4.y);
            u64 bb2 = pack2(b4.z, b4.z), bb3 = pack2(b4.w, b4.w);
            acc[0][0] = fma2(a01, bb0, acc[0][0]); acc[1][0] = fma2(a23, bb0, acc[1][0]);
            acc[0][1] = fma2(a01, bb1, acc[0][1]); acc[1][1] = fma2(a23, bb1, acc[1][1]);
            acc[0][2] = fma2(a01, bb2, acc[0][2]); acc[1][2] = fma2(a23, bb2, acc[1][2]);
            acc[0][3] = fma2(a01, bb3, acc[0][3]); acc[1][3] = fma2(a23, bb3, acc[1][3]);
        }
        __syncthreads();
    }
    #pragma unroll
    for (int mp = 0; mp < 2; mp++) {
        float2 v[4];
        #pragma unroll
        for (int n = 0; n < 4; n++) v[n] = unpack2(acc[mp][n]);
        int r0 = row0 + ty * 4 + mp * 2;
        int c0 = col0 + tx * 4;
        #pragma unroll
        for (int n = 0; n < 4; n++) {
            g_h[(size_t)(r0 + 0) * HD + c0 + n] = v[n].x;
            g_h[(size_t)(r0 + 1) * HD + c0 + n] = v[n].y;
        }
        __half2 hx0 = __floats2half2_rn(v[0].x, v[1].x);
        __half2 hx1 = __floats2half2_rn(v[2].x, v[3].x);
        __half2 hy0 = __floats2half2_rn(v[0].y, v[1].y);
        __half2 hy1 = __floats2half2_rn(v[2].y, v[3].y);
        *(__half2*)&g_hh[(size_t)(r0 + 0) * HD + c0]     = hx0;
        *(__half2*)&g_hh[(size_t)(r0 + 0) * HD + c0 + 2] = hx1;
        *(__half2*)&g_hh[(size_t)(r0 + 1) * HD + c0]     = hy0;
        *(__half2*)&g_hh[(size_t)(r0 + 1) * HD + c0 + 2] = hy1;
    }
}

// ---------------- kernel 2: scores + shifted exp tables -----------------------
__global__ void __launch_bounds__(256) scores_k(const float* __restrict__ a1,
                                                const float* __restrict__ a2) {
    __shared__ float s1[Dd], s2[Dd];
    if (threadIdx.x < Dd)            s1[threadIdx.x]      = a1[threadIdx.x];
    else if (threadIdx.x < 2 * Dd)   s2[threadIdx.x - Dd] = a2[threadIdx.x - Dd];
    __syncthreads();

    const int g  = blockIdx.x * 256 + threadIdx.x;
    const int n  = g >> 2;
    const int hh = g & 3;
    const float* hrow = g_h + (size_t)n * HD + hh * Dd;
    float si = 0.f, sj = 0.f;
    #pragma unroll
    for (int q = 0; q < 16; q++) {
        float4 hv = ((const float4*)hrow)[q];
        si = fmaf(hv.x, s1[4*q+0], si); sj = fmaf(hv.x, s2[4*q+0], sj);
        si = fmaf(hv.y, s1[4*q+1], si); sj = fmaf(hv.y, s2[4*q+1], sj);
        si = fmaf(hv.z, s1[4*q+2], si); sj = fmaf(hv.z, s2[4*q+2], sj);
        si = fmaf(hv.w, s1[4*q+3], si); sj = fmaf(hv.w, s2[4*q+3], sj);
    }
    g_si[g]  = si;                     g_sj[g]  = sj;
    g_eip[g] = __expf(si - 2.f);       g_ejp[g] = __expf(sj - 2.f);
    g_ein[g] = __expf(0.2f*si - 2.f);  g_ejn[g] = __expf(0.2f*sj - 2.f);
}

// ---------------- kernel 2b: pack j-side tables (SoA per 64-chunk) ------------
__global__ void __launch_bounds__(256) tab_pack() {
    const int g  = blockIdx.x * 256 + threadIdx.x;   // 0 .. NN/2*Hh-1
    const int np = g >> 2;
    const int hh = g & 3;
    const int na = 2 * np, nb = 2 * np + 1;
    u32 s  = h2_u32(__floats2half2_rn(g_sj [na*Hh+hh], g_sj [nb*Hh+hh]));
    u32 ep = h2_u32(__floats2half2_rn(g_ejp[na*Hh+hh], g_ejp[nb*Hh+hh]));
    u32 en = h2_u32(__floats2half2_rn(g_ejn[na*Hh+hh], g_ejn[nb*Hh+hh]));
    const int base = (np >> 5) * 384 + hh * 96 + (np & 31);
    g_tab2[base +  0] = s;
    g_tab2[base + 32] = ep;
    g_tab2[base + 64] = en;
}

// ---------------- kernel 3: pipelined tensor-core aggregation -----------------
// 512 threads (16 warps). grid (64 i-tiles, 2 j-splits).
// hS x3 (cp.async), wS x2 (register-pipelined Phase A), tab x3 (cp.async).
// One __syncthreads per chunk.
#define HS_STRIDE_B  528                       // 264 halves: 256 data + ones col @512
#define HS_BUF_B     (64 * HS_STRIDE_B)        // 33792
#define WS_BUF_B     32768                     // 4 heads x 64 rows x 128B
#define OFF_HS   0
#define OFF_WS   (3 * HS_BUF_B)                // 101376
#define OFF_TAB  (OFF_WS + 2 * WS_BUF_B)       // 166912
#define TAB_BUF_B 1536
#define SMEM_BYTES_AGG (OFF_TAB + 3 * TAB_BUF_B)   // 171520

__global__ void __launch_bounds__(512, 1) gat_mma(const int* __restrict__ adj) {
    extern __shared__ char sm[];
    const u32 smem_u32 = (u32)__cvta_generic_to_shared(sm);

    const int t     = threadIdx.x;
    const int lane  = t & 31;
    const int wid   = t >> 5;
    const int i0    = blockIdx.x * TI;
    const int split = blockIdx.y;
    const int jbase0 = split * JPER;

    // Phase-A ids: 1 i-row per thread, 4 j-pairs (grp)
    const int iA  = t >> 3;                    // 0..63
    const int grp = t & 7;                     // 0..7

    // MMA warp tiling: 2 i-groups (32 rows) x 8 col-groups (32 cols)
    const int iw2  = (wid & 1) * 32;
    const int cw8  = wid >> 1;                 // 0..7
    const int ncol = cw8 * 32;                 // halves
    const int headA = cw8 >> 1;
    const bool doZ  = (cw8 & 1) == 0;
    const int rowL = (lane & 7) + (lane & 8);
    const int colL = (lane >> 4) << 3;

    // i-side constants (1 i-row): rsi dup-half2 and packed (eip,ein) per head
    u32 rsi2[4], rpn[4];
    #pragma unroll
    for (int h = 0; h < 4; h++) {
        const size_t gix = (size_t)(i0 + iA) * Hh + h;
        rsi2[h] = h2_u32(__float2half2_rn(g_si[gix]));
        rpn[h]  = h2_u32(__halves2half2(__float2half(g_eip[gix]),
                                        __float2half(g_ein[gix])));
    }
    const __half2 hz = __float2half2_rn(0.f);

    float acc[8][4];
    #pragma unroll
    for (int q = 0; q < 8; q++)
        #pragma unroll
        for (int r = 0; r < 4; r++) acc[q][r] = 0.f;
    float zacc[2][4];
    #pragma unroll
    for (int m = 0; m < 2; m++)
        #pragma unroll
        for (int r = 0; r < 4; r++) zacc[m][r] = 0.f;

    // ---- staging helpers ----
    auto stage_h = [&](int c) {                // hS(c) -> buffer c%3
        const u32 hb = smem_u32 + OFF_HS + (u32)(c % 3) * HS_BUF_B;
        const char* gsrc = (const char*)(g_hh + (size_t)(jbase0 + c * JC) * HD);
        #pragma unroll
        for (int r = 0; r < 4; r++) {
            int v = r * 512 + t;               // 0..2047 int4
            int j = v >> 5, c16 = v & 31;
            cp_async16(hb + j * HS_STRIDE_B + c16 * 16, gsrc + (size_t)v * 16);
        }
    };
    auto stage_tab = [&](int c) {              // tab(c) -> buffer c%3
        if (t < 96) {
            const u32 tb = smem_u32 + OFF_TAB + (u32)(c % 3) * TAB_BUF_B;
            const char* tsrc = (const char*)(g_tab2 + (size_t)((jbase0 + c * JC) >> 6) * 384);
            cp_async16(tb + t * 16, tsrc + t * 16);
        }
    };
    // ---- Phase A: compute w(c) from av regs + tab smem, STS into wS[c&1] ----
    auto phaseA = [&](int c, int4 av0, int4 av1) {
        const u32 tb = smem_u32 + OFF_TAB + (u32)(c % 3) * TAB_BUF_B;
        const int avv[8] = {av0.x, av0.y, av0.z, av0.w, av1.x, av1.y, av1.z, av1.w};
        u32 em[4];
        #pragma unroll
        for (int p = 0; p < 4; p++)
            em[p] = h2_u32(__floats2half2_rn((float)avv[2*p], (float)avv[2*p+1]));
        const u32 wsbase = smem_u32 + OFF_WS + (u32)(c & 1) * WS_BUF_B
                         + (u32)iA * 128 + (((u32)grp * 16) ^ (((u32)(iA & 7)) << 4));
        #pragma unroll
        for (int h = 0; h < 4; h++) {
            int4 ts, tp, tn;
            asm volatile("ld.shared.v4.u32 {%0,%1,%2,%3}, [%4];"
                : "=r"(ts.x),"=r"(ts.y),"=r"(ts.z),"=r"(ts.w)
                : "r"(tb + (u32)(h * 96      + grp * 4) * 4));
            asm volatile("ld.shared.v4.u32 {%0,%1,%2,%3}, [%4];"
                : "=r"(tp.x),"=r"(tp.y),"=r"(tp.z),"=r"(tp.w)
                : "r"(tb + (u32)(h * 96 + 32 + grp * 4) * 4));
            asm volatile("ld.shared.v4.u32 {%0,%1,%2,%3}, [%4];"
                : "=r"(tn.x),"=r"(tn.y),"=r"(tn.z),"=r"(tn.w)
                : "r"(tb + (u32)(h * 96 + 64 + grp * 4) * 4));
            const u32 tsv[4] = {(u32)ts.x,(u32)ts.y,(u32)ts.z,(u32)ts.w};
            const u32 tpv[4] = {(u32)tp.x,(u32)tp.y,(u32)tp.z,(u32)tp.w};
            const u32 tnv[4] = {(u32)tn.x,(u32)tn.y,(u32)tn.z,(u32)tn.w};
            __half2 rp   = u32_h2(rpn[h]);
            __half2 rep2 = __low2half2(rp);
            __half2 ren2 = __high2half2(rp);
            u32 wv[4];
            #pragma unroll
            for (int p = 0; p < 4; p++) {
                __half2 t2 = __hadd2(u32_h2(rsi2[h]), u32_h2(tsv[p]));
                __half2 p2 = __hmul2(rep2, u32_h2(tpv[p]));
                __half2 n2 = __hmul2(ren2, u32_h2(tnv[p]));
                __half2 m2 = __hge2(t2, hz);
                __half2 w2 = __hfma2(m2, __hsub2(p2, n2), n2);
                wv[p] = h2_u32(__hmul2(w2, u32_h2(em[p])));
            }
            asm volatile("st.shared.v4.u32 [%0], {%1,%2,%3,%4};"
                :: "r"(wsbase + (u32)h * 8192),
                   "r"(wv[0]), "r"(wv[1]), "r"(wv[2]), "r"(wv[3]));
        }
    };
    auto adj_ld = [&](int c, int4& av0, int4& av1) {
        const int* ar = adj + (size_t)(i0 + iA) * NN + jbase0 + c * JC + grp * 8;
        av0 = ((const int4*)ar)[0];
        av1 = ((const int4*)ar)[1];
    };

    // ---- prologue ----
    if (t < 192) {                              // ones columns, all 3 hS buffers
        int buf = t >> 6, j = t & 63;
        *(int4*)(sm + OFF_HS + buf * HS_BUF_B + j * HS_STRIDE_B + 512) =
            make_int4(0x3C00, 0, 0, 0);
    }
    stage_tab(0);              cp_commit();     // G-3: tab(0)
    stage_h(0); stage_tab(1);  cp_commit();     // G-2: hS(0), tab(1)
    stage_h(1); stage_tab(2);  cp_commit();     // G-1: hS(1), tab(2)
    cp_waitN<2>();                              // tab(0) landed
    __syncthreads();                            // publish tab(0) + ones
    {
        int4 av0, av1;
        adj_ld(0, av0, av1);
        phaseA(0, av0, av1);                    // fill wS[0]
    }
    cp_waitN<1>();                              // hS(0), tab(1) landed
    __syncthreads();                            // publish wS[0], hS(0), tab(1)

    // ---- main loop: one barrier per chunk ----
    for (int c = 0; c < NCHUNK; c++) {
        // early adj LDG for c+1 (consumed after MMA; latency hidden)
        int4 av0, av1;
        if (c + 1 < NCHUNK) adj_ld(c + 1, av0, av1);

        // Phase B: MMA(c)
        const u32 hbase  = smem_u32 + OFF_HS + (u32)(c % 3) * HS_BUF_B;
        const u32 wsrd   = smem_u32 + OFF_WS + (u32)(c & 1) * WS_BUF_B
                         + (u32)(headA * 8192);
        #pragma unroll
        for (int ks = 0; ks < 4; ks++) {
            u32 A0[4], A1[4];
            {
                const int r0 = iw2 + rowL, r1 = iw2 + 16 + rowL;
                const u32 cb = (u32)(ks * 32) + ((u32)(lane >> 4) << 4);
                u32 a0a = wsrd + (u32)r0 * 128 + (cb ^ (((u32)(r0 & 7)) << 4));
                u32 a1a = wsrd + (u32)r1 * 128 + (cb ^ (((u32)(r1 & 7)) << 4));
                ldsm_x4(A0[0], A0[1], A0[2], A0[3], a0a);
                ldsm_x4(A1[0], A1[1], A1[2], A1[3], a1a);
            }
            if (doZ) {
                u32 bo0, bo1;
                ldsm_x2_t(bo0, bo1, hbase + (u32)(ks * 16 + rowL) * HS_STRIDE_B + 512);
                mma16816(zacc[0], A0[0], A0[1], A0[2], A0[3], bo0, bo1);
                mma16816(zacc[1], A1[0], A1[1], A1[2], A1[3], bo0, bo1);
            }
            #pragma unroll
            for (int p = 0; p < 2; p++) {
                u32 b0, b1, b2, b3;
                u32 ba = hbase + (u32)(ks * 16 + rowL) * HS_STRIDE_B
                       + (u32)(ncol + p * 16 + colL) * 2;
                ldsm_x4_t(b0, b1, b2, b3, ba);
                mma16816(acc[p*2 + 0], A0[0], A0[1], A0[2], A0[3], b0, b1);
                mma16816(acc[p*2 + 1], A0[0], A0[1], A0[2], A0[3], b2, b3);
                mma16816(acc[4 + p*2 + 0], A1[0], A1[1], A1[2], A1[3], b0, b1);
                mma16816(acc[4 + p*2 + 1], A1[0], A1[1], A1[2], A1[3], b2, b3);
            }
        }

        // Phase A for c+1 (writes wS[(c+1)&1], read only next iter)
        if (c + 1 < NCHUNK) phaseA(c + 1, av0, av1);

        // stage hS(c+2) + tab(c+3); always commit to keep group count aligned
        if (c + 2 < NCHUNK) stage_h(c + 2);
        if (c + 3 < NCHUNK) stage_tab(c + 3);
        cp_commit();
        cp_waitN<1>();        // hS(c+1) + tab(c+2) landed
        __syncthreads();      // publish wS[(c+1)&1], hS(c+1), tab(c+2)
    }

    // ---- writeback partials ----
    {
        float* base = g_part + (size_t)split * NN * HD;
        const int cc = (lane & 3) * 2;
        #pragma unroll
        for (int m = 0; m < 2; m++) {
            const int r0 = i0 + iw2 + m * 16 + (lane >> 2);
            #pragma unroll
            for (int n = 0; n < 4; n++) {
                const int col = ncol + n * 8 + cc;
                *(float2*)&base[(size_t)(r0    ) * HD + col] =
                    make_float2(acc[m*4+n][0], acc[m*4+n][1]);
                *(float2*)&base[(size_t)(r0 + 8) * HD + col] =
                    make_float2(acc[m*4+n][2], acc[m*4+n][3]);
            }
        }
    }
    if (doZ && (lane & 3) == 0) {
        float* zb = g_Z + (size_t)split * NN * Hh;
        #pragma unroll
        for (int m = 0; m < 2; m++) {
            const int r0 = i0 + iw2 + m * 16 + (lane >> 2);
            zb[(size_t)(r0    ) * Hh + headA] = zacc[m][0];
            zb[(size_t)(r0 + 8) * Hh + headA] = zacc[m][2];
        }
    }
}

// ---------------- kernel 4: combine splits + normalize -----------------------
__global__ void __launch_bounds__(256) epilogue_k(float* __restrict__ out) {
    int e = blockIdx.x * 256 + threadIdx.x;
    float p = g_part[e] + g_part[(size_t)NN * HD + e];
    int i = e >> 8;
    int head = (e & 255) >> 6;
    float z = g_Z[i * Hh + head] + g_Z[(size_t)NN * Hh + i * Hh + head];
    out[e] = p / z;
}

// ---------------- launch ------------------------------------------------------
extern "C" void kernel_launch(void* const* d_in, const int* in_sizes, int n_in,
                              void* d_out, int out_size) {
    const float* x   = (const float*)d_in[0];
    const int*   adj = (const int*)  d_in[1];
    const float* W   = (const float*)d_in[2];
    const float* a1  = (const float*)d_in[3];
    const float* a2  = (const float*)d_in[4];
    float* out = (float*)d_out;

    cudaFuncSetAttribute(gat_mma, cudaFuncAttributeMaxDynamicSharedMemorySize,
                         SMEM_BYTES_AGG);

    gemm_xw  <<<dim3(HD/64, NN/64), 256>>>(x, W);
    scores_k <<<(NN*Hh)/256, 256>>>(a1, a2);
    tab_pack <<<(NN/2*Hh)/256, 256>>>();
    gat_mma  <<<dim3(NN/TI, JSPLIT), 512, SMEM_BYTES_AGG>>>(adj);
    epilogue_k<<<(NN*HD)/256, 256>>>(out);
}